// round 5
// baseline (speedup 1.0000x reference)
#include <cuda_runtime.h>
#include <cstdint>

// WeightedEmbeddingBag: B=4096, N=200, M=26, VOCAB=100000, D=128
// Inputs (int64 in the reference is materialized as int32 — JAX x64 off):
//   d_in[0] input              int32  [B, N]
//   d_in[1] per_sample_weights fp32   [B, N]
//   d_in[2] offsets            int32  [B, M]  (sorted per row, in [0, N))
//   d_in[3] emb_weight         fp32   [VOCAB, D]
// Output: fp32 [B, M, D]
//
// out[b,m,:] = sum_{n=start}^{end} w[b,n]*emb[id[b,n]],
//   start = (m==0 ? 0 : offsets[b,m-1]+1), end = offsets[b,m]  (inclusive;
//   empty when end < start -> zeros). Direct segment sum == cumsum-difference
//   up to fp32 rounding (~1e-7), far inside the 1e-3 gate.
//
// One warp per (b,m): 106K independent warps (vs 4K serial walkers before).
// Lane t owns D-slice [4t,4t+4) as float4. Ids/weights loaded coalesced
// (one lane each), shfl-broadcast; embedding rows gathered in batches of 8
// predicated LDG.128 for MLP=8 per warp.

#define BB 4096
#define NN 200
#define MM 26
#define WARPS_PER_CTA 4
#define BATCH 8

__global__ __launch_bounds__(32 * WARPS_PER_CTA)
void ebag_seg_kernel(const int*    __restrict__ input,
                     const float*  __restrict__ psw,
                     const int*    __restrict__ offsets,
                     const float4* __restrict__ emb4,   // [VOCAB, 32] float4
                     float4*       __restrict__ out4)   // [B*M, 32] float4
{
    const int lane = threadIdx.x & 31;
    const int widx = blockIdx.x * WARPS_PER_CTA + (threadIdx.x >> 5);
    if (widx >= BB * MM) return;

    const int b = widx / MM;
    const int m = widx - b * MM;

    const int* offb = offsets + (size_t)b * MM;
    int end   = offb[m];                         // inclusive
    int start = (m == 0) ? 0 : offb[m - 1] + 1;
    // Defensive clamps (fail correctness cleanly, never fault):
    if (end   > NN - 1) end   = NN - 1;
    if (start < 0)      start = 0;

    const int*   in_b = input + (size_t)b * NN;
    const float* w_b  = psw   + (size_t)b * NN;

    float4 acc = make_float4(0.f, 0.f, 0.f, 0.f);

    for (int base = start; base <= end; base += 32) {
        const int cnt = min(32, end - base + 1);

        int   myid = 0;
        float myw  = 0.f;
        if (lane < cnt) {
            myid = in_b[base + lane];
            myw  = w_b[base + lane];
        }

        for (int r0 = 0; r0 < cnt; r0 += BATCH) {
            const int nb = min(BATCH, cnt - r0);
            float4 v[BATCH];
            float  wr[BATCH];

            #pragma unroll
            for (int j = 0; j < BATCH; j++) {
                const int r   = (r0 + j) & 31;
                const int idr = __shfl_sync(0xffffffffu, myid, r);
                wr[j]         = __shfl_sync(0xffffffffu, myw,  r);
                if (j < nb)
                    v[j] = emb4[(size_t)idr * 32 + lane];
            }

            #pragma unroll
            for (int j = 0; j < BATCH; j++) {
                if (j < nb) {
                    acc.x = fmaf(wr[j], v[j].x, acc.x);
                    acc.y = fmaf(wr[j], v[j].y, acc.y);
                    acc.z = fmaf(wr[j], v[j].z, acc.z);
                    acc.w = fmaf(wr[j], v[j].w, acc.w);
                }
            }
        }
    }

    out4[(size_t)widx * 32 + lane] = acc;
}

extern "C" void kernel_launch(void* const* d_in, const int* in_sizes, int n_in,
                              void* d_out, int out_size)
{
    const int*    input   = (const int*)   d_in[0];
    const float*  psw     = (const float*) d_in[1];
    const int*    offsets = (const int*)   d_in[2];
    const float4* emb4    = (const float4*)d_in[3];
    float4*       out4    = (float4*)d_out;

    const int n_warps = BB * MM;                       // 106496
    const int n_ctas  = (n_warps + WARPS_PER_CTA - 1) / WARPS_PER_CTA;
    ebag_seg_kernel<<<n_ctas, 32 * WARPS_PER_CTA>>>(input, psw, offsets, emb4, out4);
}

// round 6
// speedup vs baseline: 2.4648x; 2.4648x over previous
#include <cuda_runtime.h>
#include <cstdint>

// WeightedEmbeddingBag: B=4096, N=200, M=26, VOCAB=100000, D=128
//   d_in[0] input   int32 [B,N]   d_in[1] weights fp32 [B,N]
//   d_in[2] offsets int32 [B,M]   d_in[3] emb     fp32 [VOCAB,D]
// Output fp32 [B,M,D].
//
// out[b,m,:] = sum over segment of w*emb[id], segments from cumsum-difference.
// Warp-per-batch running accumulator with snapshots at offset boundaries
// (identical numerics to the reference construction).
//
// R6: ids/weights preloaded to SMEM (kills the dependent id->gather chain),
// gather loop unrolled x8 -> 8 independent 512B LDG.128 in flight per warp.

#define BB 4096
#define NN 200
#define MM 26
#define WARPS_PER_CTA 4
#define UNROLL 8

__global__ __launch_bounds__(32 * WARPS_PER_CTA)
void ebag_kernel(const int*    __restrict__ input,
                 const float*  __restrict__ psw,
                 const int*    __restrict__ offsets,
                 const float4* __restrict__ emb4,   // [VOCAB, 32] float4
                 float4*       __restrict__ out4)   // [B, M, 32] float4
{
    const int wid  = threadIdx.x >> 5;
    const int lane = threadIdx.x & 31;
    const int b    = blockIdx.x * WARPS_PER_CTA + wid;
    if (b >= BB) return;

    __shared__ int   s_id[WARPS_PER_CTA][NN];
    __shared__ float s_w [WARPS_PER_CTA][NN];
    __shared__ int   s_off[WARPS_PER_CTA][32];

    const int*   in_b = input + (size_t)b * NN;
    const float* w_b  = psw   + (size_t)b * NN;

    // Coalesced one-time preload of this batch row's ids + weights.
    #pragma unroll
    for (int n = lane; n < NN; n += 32) {
        s_id[wid][n] = in_b[n];
        s_w [wid][n] = w_b[n];
    }
    if (lane < MM)
        s_off[wid][lane] = offsets[(size_t)b * MM + lane];
    __syncwarp();

    float4* o_b = out4 + (size_t)b * MM * 32;

    int nmax = s_off[wid][MM - 1];
    if (nmax > NN - 1) nmax = NN - 1;   // defensive: fail clean, never fault
    if (nmax < 0)      nmax = 0;

    float4 acc  = make_float4(0.f, 0.f, 0.f, 0.f);
    float4 snap = make_float4(0.f, 0.f, 0.f, 0.f);
    int m   = 0;
    int cur = s_off[wid][0];

    for (int n0 = 0; n0 <= nmax; n0 += UNROLL) {
        // Issue UNROLL independent 512B gathers (tail iters clamp to nmax:
        // harmless duplicate loads, results discarded by the j-loop guard).
        float4 v[UNROLL];
        #pragma unroll
        for (int j = 0; j < UNROLL; j++) {
            int n = n0 + j;
            int nc = (n <= nmax) ? n : nmax;
            v[j] = emb4[(size_t)s_id[wid][nc] * 32 + lane];
        }

        #pragma unroll
        for (int j = 0; j < UNROLL; j++) {
            const int n = n0 + j;
            if (n <= nmax) {
                const float w = s_w[wid][n];
                acc.x = fmaf(w, v[j].x, acc.x);
                acc.y = fmaf(w, v[j].y, acc.y);
                acc.z = fmaf(w, v[j].z, acc.z);
                acc.w = fmaf(w, v[j].w, acc.w);

                // Emit every segment ending at n (duplicate offsets -> empty
                // segments -> exact zeros, matching the reference).
                while (cur == n) {
                    float4 r = make_float4(acc.x - snap.x, acc.y - snap.y,
                                           acc.z - snap.z, acc.w - snap.w);
                    o_b[m * 32 + lane] = r;
                    snap = acc;
                    m++;
                    cur = (m < MM) ? s_off[wid][m] : -1;
                }
            }
        }
    }
}

extern "C" void kernel_launch(void* const* d_in, const int* in_sizes, int n_in,
                              void* d_out, int out_size)
{
    const int*    input   = (const int*)   d_in[0];
    const float*  psw     = (const float*) d_in[1];
    const int*    offsets = (const int*)   d_in[2];
    const float4* emb4    = (const float4*)d_in[3];
    float4*       out4    = (float4*)d_out;

    dim3 grid(BB / WARPS_PER_CTA);
    dim3 block(32 * WARPS_PER_CTA);
    ebag_kernel<<<grid, block>>>(input, psw, offsets, emb4, out4);
}